// round 3
// baseline (speedup 1.0000x reference)
#include <cuda_runtime.h>
#include <math_constants.h>

#define NN   512
#define MMM  2048
#define FEATD 1024
#define NG   16
#define DG   64

// ---------------- device scratch (no allocations allowed) ----------------
__device__ float g_q[NG * NN * DG];        // (q + u + bias) / 8, layout [g][n][d]
__device__ float g_k[NG * MMM * DG];       // k + bias,           layout [g][m][d]
__device__ float g_v[NG * MMM * DG];       // ref_feat @ Wv^T,    layout [g][m][d]
__device__ float g_logw[NG * NN * MMM];    // log(relu(Wg.pe)+1e-6), [g][n][m]

// =====================================================================
// Kernel 1: position embedding -> grouped 1x1 conv -> log prior
// one thread per (n,m) pair; computes all 16 group values
// =====================================================================
__global__ __launch_bounds__(256) void pos_kernel(
    const float* __restrict__ bbox, const float* __restrict__ ref_bbox,
    const float* __restrict__ Wg_w, const float* __restrict__ Wg_b)
{
    __shared__ float sW[NG * 64];
    __shared__ float sB[NG];
    int tid = threadIdx.x;
    for (int i = tid; i < NG * 64; i += 256) sW[i] = Wg_w[i];
    if (tid < NG) sB[tid] = Wg_b[tid];
    __syncthreads();

    int idx = blockIdx.x * 256 + tid;          // 0 .. N*M-1
    int n = idx >> 11;                         // /2048
    int m = idx & (MMM - 1);

    float x0 = bbox[4 * n + 0], y0 = bbox[4 * n + 1];
    float x1 = bbox[4 * n + 2], y1 = bbox[4 * n + 3];
    float w  = x1 - x0 + 1.0f, h = y1 - y0 + 1.0f;
    float cx = 0.5f * (x0 + x1), cy = 0.5f * (y0 + y1);

    float a0 = ref_bbox[4 * m + 0], a1 = ref_bbox[4 * m + 1];
    float a2 = ref_bbox[4 * m + 2], a3 = ref_bbox[4 * m + 3];
    float wr  = a2 - a0 + 1.0f, hr = a3 - a1 + 1.0f;
    float cxr = 0.5f * (a0 + a2), cyr = 0.5f * (a1 + a3);

    float pos[4];
    pos[0] = logf(fabsf((cx - cxr) / w) + 1e-3f);
    pos[1] = logf(fabsf((cy - cyr) / h) + 1e-3f);
    pos[2] = logf(w / wr);
    pos[3] = logf(h / hr);

    // sc[f] = 100 / 1000^(f/8)
    const float sc[8] = {100.0f, 42.16965034f, 17.7827941f, 7.498942093f,
                         3.16227766f, 1.333521432f, 0.5623413252f, 0.2371373706f};

    float sv[32], cv[32];
#pragma unroll
    for (int c = 0; c < 4; c++) {
#pragma unroll
        for (int f = 0; f < 8; f++) {
            float a  = pos[c] * sc[f];
            // Cody-Waite range reduction to [-pi, pi], then fast HW trig
            float kq = rintf(a * 0.15915494309f);
            float r  = fmaf(kq, -6.2831855f, a);
            r        = fmaf(kq, 1.7484555e-7f, r);
            sv[c * 8 + f] = __sinf(r);
            cv[c * 8 + f] = __cosf(r);
        }
    }

    int base = n * MMM + m;
#pragma unroll
    for (int gi = 0; gi < NG; gi++) {
        float acc = sB[gi];
        const float4* wv = (const float4*)&sW[gi * 64];
#pragma unroll
        for (int c = 0; c < 4; c++) {
            float4 ws0 = wv[c * 4 + 0];
            float4 ws1 = wv[c * 4 + 1];
            float4 wc0 = wv[c * 4 + 2];
            float4 wc1 = wv[c * 4 + 3];
            const float* s8 = &sv[c * 8];
            const float* c8 = &cv[c * 8];
            acc = fmaf(ws0.x, s8[0], acc); acc = fmaf(ws0.y, s8[1], acc);
            acc = fmaf(ws0.z, s8[2], acc); acc = fmaf(ws0.w, s8[3], acc);
            acc = fmaf(ws1.x, s8[4], acc); acc = fmaf(ws1.y, s8[5], acc);
            acc = fmaf(ws1.z, s8[6], acc); acc = fmaf(ws1.w, s8[7], acc);
            acc = fmaf(wc0.x, c8[0], acc); acc = fmaf(wc0.y, c8[1], acc);
            acc = fmaf(wc0.z, c8[2], acc); acc = fmaf(wc0.w, c8[3], acc);
            acc = fmaf(wc1.x, c8[4], acc); acc = fmaf(wc1.y, c8[5], acc);
            acc = fmaf(wc1.z, c8[6], acc); acc = fmaf(wc1.w, c8[7], acc);
        }
        float pf = fmaxf(acc, 0.0f);
        g_logw[(size_t)gi * (NN * MMM) + base] = logf(pf + 1e-6f);
    }
}

// =====================================================================
// Kernel 2: SGEMM  C[row,o] = (sum_f A[row,f]*W[o,f] + bias[o] + uadd[o]) * scale
// stored head-major: out[(o>>6)][row][o&63].  which: 0=g_q 1=g_k 2=g_v
// BM=BN=128, BK=16, 256 threads, 8x8 microtile
// =====================================================================
__global__ __launch_bounds__(256) void gemm_kernel(
    const float* __restrict__ A, const float* __restrict__ W,
    const float* __restrict__ bias, const float* __restrict__ uadd,
    int which, int rows, float scale)
{
    __shared__ float As[16][128];
    __shared__ float Bs[16][128];

    float* outp = (which == 0) ? g_q : (which == 1) ? g_k : g_v;

    int tid = threadIdx.x;
    int tx = tid & 15, ty = tid >> 4;
    int m0 = blockIdx.x * 128;
    int n0 = blockIdx.y * 128;

    float acc[8][8];
#pragma unroll
    for (int i = 0; i < 8; i++)
#pragma unroll
        for (int j = 0; j < 8; j++) acc[i][j] = 0.0f;

    for (int k0 = 0; k0 < FEATD; k0 += 16) {
#pragma unroll
        for (int b = 0; b < 2; b++) {
            int fid = tid + b * 256;
            int r = fid >> 2, c4 = fid & 3;
            float4 va = *(const float4*)&A[(size_t)(m0 + r) * FEATD + k0 + c4 * 4];
            As[c4 * 4 + 0][r] = va.x; As[c4 * 4 + 1][r] = va.y;
            As[c4 * 4 + 2][r] = va.z; As[c4 * 4 + 3][r] = va.w;
            float4 vb = *(const float4*)&W[(size_t)(n0 + r) * FEATD + k0 + c4 * 4];
            Bs[c4 * 4 + 0][r] = vb.x; Bs[c4 * 4 + 1][r] = vb.y;
            Bs[c4 * 4 + 2][r] = vb.z; Bs[c4 * 4 + 3][r] = vb.w;
        }
        __syncthreads();
#pragma unroll
        for (int kk = 0; kk < 16; kk++) {
            float af[8], bf[8];
            *(float4*)&af[0] = *(const float4*)&As[kk][ty * 4];
            *(float4*)&af[4] = *(const float4*)&As[kk][64 + ty * 4];
            *(float4*)&bf[0] = *(const float4*)&Bs[kk][tx * 4];
            *(float4*)&bf[4] = *(const float4*)&Bs[kk][64 + tx * 4];
#pragma unroll
            for (int i = 0; i < 8; i++)
#pragma unroll
                for (int j = 0; j < 8; j++)
                    acc[i][j] = fmaf(af[i], bf[j], acc[i][j]);
        }
        __syncthreads();
    }

#pragma unroll
    for (int i = 0; i < 8; i++) {
        int row = m0 + ((i < 4) ? (ty * 4 + i) : (64 + ty * 4 + (i - 4)));
#pragma unroll
        for (int jh = 0; jh < 2; jh++) {
            int col0 = n0 + jh * 64 + tx * 4;
            float v[4];
#pragma unroll
            for (int jj = 0; jj < 4; jj++) {
                int o = col0 + jj;
                float t = acc[i][jh * 4 + jj];
                if (bias) t += __ldg(&bias[o]);
                if (uadd) t += __ldg(&uadd[o]);
                v[jj] = t * scale;
            }
            int gidx = col0 >> 6, d = col0 & 63;
            *(float4*)&outp[((size_t)gidx * rows + row) * DG + d] =
                make_float4(v[0], v[1], v[2], v[3]);
        }
    }
}

// =====================================================================
// Kernel 3: fused flash attention + output epilogue.
// block = (g, 64 q-rows), 256 threads, 64-wide m tiles, online softmax.
// Row stats replicated across the 16 tx lanes (shfl width-16 reductions).
// =====================================================================
#define STR 68
#define ATT_SMEM_BYTES (4 * 64 * STR * 4)

__global__ __launch_bounds__(256) void attn_kernel(
    float* __restrict__ out, const float* __restrict__ Wv_b)
{
    extern __shared__ float sm[];
    float* Qs = sm;
    float* Ks = sm + 64 * STR;
    float* Vs = sm + 2 * 64 * STR;
    float* Ps = sm + 3 * 64 * STR;

    int tid = threadIdx.x;
    int tx = tid & 15, ty = tid >> 4;
    int g  = blockIdx.y;
    int n0 = blockIdx.x * 64;

    // Q tile (already holds bias + u, pre-scaled by 1/8)
#pragma unroll
    for (int b = 0; b < 4; b++) {
        int fid = tid + b * 256;
        int r = fid >> 4, d4 = fid & 15;
        *(float4*)&Qs[r * STR + d4 * 4] =
            *(const float4*)&g_q[((size_t)g * NN + n0 + r) * DG + d4 * 4];
    }

    float m_run[4], l_run[4];
    float acc[4][4];
#pragma unroll
    for (int i = 0; i < 4; i++) {
        m_run[i] = -CUDART_INF_F;
        l_run[i] = 0.0f;
#pragma unroll
        for (int j = 0; j < 4; j++) acc[i][j] = 0.0f;
    }

    const float* lwbase = g_logw + (size_t)g * NN * MMM + (size_t)n0 * MMM;

    for (int m0 = 0; m0 < MMM; m0 += 64) {
        __syncthreads();   // prev AV readers done before K/V overwrite
#pragma unroll
        for (int b = 0; b < 4; b++) {
            int fid = tid + b * 256;
            int r = fid >> 4, d4 = fid & 15;
            size_t src = ((size_t)g * MMM + m0 + r) * DG + d4 * 4;
            *(float4*)&Ks[r * STR + d4 * 4] = *(const float4*)&g_k[src];
            *(float4*)&Vs[r * STR + d4 * 4] = *(const float4*)&g_v[src];
        }
        __syncthreads();

        // ---- S = Q K^T + logw;  rows ty*4+i, cols tx+16*j ----
        float s[4][4];
#pragma unroll
        for (int i = 0; i < 4; i++)
#pragma unroll
            for (int j = 0; j < 4; j++)
                s[i][j] = lwbase[(size_t)(ty * 4 + i) * MMM + m0 + tx + 16 * j];
#pragma unroll
        for (int d4 = 0; d4 < 16; d4++) {
            float4 qf[4], kf[4];
#pragma unroll
            for (int i = 0; i < 4; i++) qf[i] = *(float4*)&Qs[(ty * 4 + i) * STR + d4 * 4];
#pragma unroll
            for (int j = 0; j < 4; j++) kf[j] = *(float4*)&Ks[(tx + 16 * j) * STR + d4 * 4];
#pragma unroll
            for (int i = 0; i < 4; i++)
#pragma unroll
                for (int j = 0; j < 4; j++) {
                    s[i][j] = fmaf(qf[i].x, kf[j].x, s[i][j]);
                    s[i][j] = fmaf(qf[i].y, kf[j].y, s[i][j]);
                    s[i][j] = fmaf(qf[i].z, kf[j].z, s[i][j]);
                    s[i][j] = fmaf(qf[i].w, kf[j].w, s[i][j]);
                }
        }

        // ---- online softmax (stats replicated across tx lanes) ----
#pragma unroll
        for (int i = 0; i < 4; i++) {
            float rm = fmaxf(fmaxf(s[i][0], s[i][1]), fmaxf(s[i][2], s[i][3]));
#pragma unroll
            for (int o = 1; o < 16; o <<= 1)
                rm = fmaxf(rm, __shfl_xor_sync(0xffffffffu, rm, o));
            float mnew  = fmaxf(m_run[i], rm);
            float alpha = __expf(m_run[i] - mnew);   // first iter: exp(-inf)=0
            m_run[i] = mnew;
            float rs = 0.0f;
#pragma unroll
            for (int j = 0; j < 4; j++) {
                s[i][j] = __expf(s[i][j] - mnew);
                rs += s[i][j];
            }
#pragma unroll
            for (int o = 1; o < 16; o <<= 1)
                rs += __shfl_xor_sync(0xffffffffu, rs, o);
            l_run[i] = l_run[i] * alpha + rs;
#pragma unroll
            for (int j = 0; j < 4; j++) {
                acc[i][j] *= alpha;
                Ps[(ty * 4 + i) * STR + tx + 16 * j] = s[i][j];
            }
        }
        __syncthreads();

        // ---- acc += P @ V ;  output dims tx*4 .. tx*4+3 ----
#pragma unroll 8
        for (int mm = 0; mm < 64; mm++) {
            float4 v4 = *(float4*)&Vs[mm * STR + tx * 4];
#pragma unroll
            for (int i = 0; i < 4; i++) {
                float pv = Ps[(ty * 4 + i) * STR + mm];
                acc[i][0] = fmaf(pv, v4.x, acc[i][0]);
                acc[i][1] = fmaf(pv, v4.y, acc[i][1]);
                acc[i][2] = fmaf(pv, v4.z, acc[i][2]);
                acc[i][3] = fmaf(pv, v4.w, acc[i][3]);
            }
        }
    }

    // ---- epilogue: normalize + Wv_b ----
#pragma unroll
    for (int i = 0; i < 4; i++) {
        float inv = __frcp_rn(l_run[i]);
        int row = n0 + ty * 4 + i;
        int o0  = g * DG + tx * 4;
        float4 bv = *(const float4*)&Wv_b[o0];
        float4 r4 = make_float4(acc[i][0] * inv + bv.x, acc[i][1] * inv + bv.y,
                                acc[i][2] * inv + bv.z, acc[i][3] * inv + bv.w);
        *(float4*)&out[(size_t)row * FEATD + o0] = r4;
    }
}

// =====================================================================
extern "C" void kernel_launch(void* const* d_in, const int* in_sizes, int n_in,
                              void* d_out, int out_size) {
    const float* bbox     = (const float*)d_in[0];
    const float* ref_bbox = (const float*)d_in[1];
    const float* roi_feat = (const float*)d_in[2];
    const float* ref_feat = (const float*)d_in[3];
    const float* Wg_w     = (const float*)d_in[4];
    const float* Wg_b     = (const float*)d_in[5];
    const float* Wq_w     = (const float*)d_in[6];
    const float* Wq_b     = (const float*)d_in[7];
    const float* Wk_w     = (const float*)d_in[8];
    const float* Wk_b     = (const float*)d_in[9];
    const float* Wv_w     = (const float*)d_in[10];
    const float* Wv_b     = (const float*)d_in[11];
    const float* u        = (const float*)d_in[12];
    float* out = (float*)d_out;

    // idempotent, called every time (no static guards allowed)
    cudaFuncSetAttribute(attn_kernel,
                         cudaFuncAttributeMaxDynamicSharedMemorySize,
                         ATT_SMEM_BYTES);

    pos_kernel<<<(NN * MMM) / 256, 256>>>(bbox, ref_bbox, Wg_w, Wg_b);
    gemm_kernel<<<dim3(NN / 128, FEATD / 128), 256>>>(
        roi_feat, Wq_w, Wq_b, u, 0, NN, 0.125f);
    gemm_kernel<<<dim3(MMM / 128, FEATD / 128), 256>>>(
        ref_feat, Wk_w, Wk_b, nullptr, 1, MMM, 1.0f);
    gemm_kernel<<<dim3(MMM / 128, FEATD / 128), 256>>>(
        ref_feat, Wv_w, nullptr, nullptr, 2, MMM, 1.0f);
    attn_kernel<<<dim3(NN / 64, NG), 256, ATT_SMEM_BYTES>>>(out, Wv_b);
}

// round 4
// speedup vs baseline: 1.4463x; 1.4463x over previous
#include <cuda_runtime.h>
#include <math_constants.h>

#define NN   512
#define MMM  2048
#define FEATD 1024
#define NG   16
#define DG   64

typedef unsigned long long u64;

// ---------------- packed f32x2 helpers ----------------
__device__ __forceinline__ u64 pack2(float lo, float hi) {
    u64 r; asm("mov.b64 %0, {%1,%2};" : "=l"(r) : "f"(lo), "f"(hi)); return r;
}
__device__ __forceinline__ float2 unpack2(u64 a) {
    float2 v; asm("mov.b64 {%0,%1}, %2;" : "=f"(v.x), "=f"(v.y) : "l"(a)); return v;
}
__device__ __forceinline__ void fma2(u64 &d, u64 a, u64 b) {
    asm("fma.rn.f32x2 %0, %1, %2, %0;" : "+l"(d) : "l"(a), "l"(b));
}
__device__ __forceinline__ void mul2(u64 &d, u64 a) {
    asm("mul.rn.f32x2 %0, %0, %1;" : "+l"(d) : "l"(a));
}

union F4u { float4 v; u64 p[2]; };

// ---------------- device scratch (no allocations allowed) ----------------
__device__ float g_q[NG * NN * DG];        // (q + u + bias) / 8, [g][n][d]
__device__ float g_k[NG * MMM * DG];       // k + bias,           [g][m][d]
__device__ float g_v[NG * MMM * DG];       // ref_feat @ Wv^T,    [g][m][d]
__device__ float g_logw[NG * NN * MMM];    // log(relu(Wg.pe)+1e-6), [g][n][m]

// =====================================================================
// Kernel 1: position embedding -> grouped 1x1 conv -> log prior
// =====================================================================
__global__ __launch_bounds__(256) void pos_kernel(
    const float* __restrict__ bbox, const float* __restrict__ ref_bbox,
    const float* __restrict__ Wg_w, const float* __restrict__ Wg_b)
{
    __shared__ float sW[NG * 64];
    __shared__ float sB[NG];
    int tid = threadIdx.x;
    for (int i = tid; i < NG * 64; i += 256) sW[i] = Wg_w[i];
    if (tid < NG) sB[tid] = Wg_b[tid];
    __syncthreads();

    int idx = blockIdx.x * 256 + tid;          // 0 .. N*M-1
    int n = idx >> 11;
    int m = idx & (MMM - 1);

    float x0 = bbox[4 * n + 0], y0 = bbox[4 * n + 1];
    float x1 = bbox[4 * n + 2], y1 = bbox[4 * n + 3];
    float w  = x1 - x0 + 1.0f, h = y1 - y0 + 1.0f;
    float cx = 0.5f * (x0 + x1), cy = 0.5f * (y0 + y1);

    float a0 = ref_bbox[4 * m + 0], a1 = ref_bbox[4 * m + 1];
    float a2 = ref_bbox[4 * m + 2], a3 = ref_bbox[4 * m + 3];
    float wr  = a2 - a0 + 1.0f, hr = a3 - a1 + 1.0f;
    float cxr = 0.5f * (a0 + a2), cyr = 0.5f * (a1 + a3);

    float pos[4];
    pos[0] = __logf(fabsf((cx - cxr) / w) + 1e-3f);
    pos[1] = __logf(fabsf((cy - cyr) / h) + 1e-3f);
    pos[2] = __logf(w / wr);
    pos[3] = __logf(h / hr);

    const float sc[8] = {100.0f, 42.16965034f, 17.7827941f, 7.498942093f,
                         3.16227766f, 1.333521432f, 0.5623413252f, 0.2371373706f};

    // packed sin/cos pairs: svp[c*4+fp] = (sin_{2fp}, sin_{2fp+1})
    u64 svp[16], cvp[16];
#pragma unroll
    for (int c = 0; c < 4; c++) {
#pragma unroll
        for (int fp = 0; fp < 4; fp++) {
            float s0, s1, c0, c1;
            {
                float a  = pos[c] * sc[2 * fp];
                float kq = rintf(a * 0.15915494309f);
                float r  = fmaf(kq, -6.2831855f, a);
                r        = fmaf(kq, 1.7484555e-7f, r);
                s0 = __sinf(r); c0 = __cosf(r);
            }
            {
                float a  = pos[c] * sc[2 * fp + 1];
                float kq = rintf(a * 0.15915494309f);
                float r  = fmaf(kq, -6.2831855f, a);
                r        = fmaf(kq, 1.7484555e-7f, r);
                s1 = __sinf(r); c1 = __cosf(r);
            }
            svp[c * 4 + fp] = pack2(s0, s1);
            cvp[c * 4 + fp] = pack2(c0, c1);
        }
    }

    int base = n * MMM + m;
#pragma unroll
    for (int gi = 0; gi < NG; gi++) {
        union { float4 v[16]; u64 p[32]; } Wr;
#pragma unroll
        for (int t = 0; t < 16; t++)
            Wr.v[t] = *(const float4*)&sW[gi * 64 + t * 4];
        u64 a2p = pack2(sB[gi], 0.0f);
#pragma unroll
        for (int c = 0; c < 4; c++) {
#pragma unroll
            for (int fp = 0; fp < 4; fp++) {
                fma2(a2p, Wr.p[c * 8 + fp],     svp[c * 4 + fp]);
                fma2(a2p, Wr.p[c * 8 + 4 + fp], cvp[c * 4 + fp]);
            }
        }
        float2 t2 = unpack2(a2p);
        float pf = fmaxf(t2.x + t2.y, 0.0f);
        g_logw[(size_t)gi * (NN * MMM) + base] = __logf(pf + 1e-6f);
    }
}

// =====================================================================
// Kernel 2: fused Q/K/V SGEMM (blockIdx.z selects which), double-buffered,
// f32x2-packed inner loop.  C = (A @ W^T + bias + uadd) * scale,
// stored head-major: out[(o>>6)][row][o&63]
// =====================================================================
__global__ __launch_bounds__(256, 2) void gemm3_kernel(
    const float* __restrict__ roi, const float* __restrict__ ref,
    const float* __restrict__ Wq, const float* __restrict__ Wqb,
    const float* __restrict__ uvec,
    const float* __restrict__ Wk, const float* __restrict__ Wkb,
    const float* __restrict__ Wv)
{
    __shared__ float As[2][16][128];
    __shared__ float Bs[2][16][128];

    int which = blockIdx.z;
    const float *A, *W, *bias, *uadd;
    float scale; int rows; float* outp;
    if (which == 0) {
        if (blockIdx.x >= NN / 128) return;
        A = roi; W = Wq; bias = Wqb; uadd = uvec; scale = 0.125f; rows = NN;  outp = g_q;
    } else if (which == 1) {
        A = ref; W = Wk; bias = Wkb; uadd = nullptr; scale = 1.0f; rows = MMM; outp = g_k;
    } else {
        A = ref; W = Wv; bias = nullptr; uadd = nullptr; scale = 1.0f; rows = MMM; outp = g_v;
    }

    int tid = threadIdx.x;
    int tx = tid & 15, ty = tid >> 4;
    int m0 = blockIdx.x * 128;
    int n0 = blockIdx.y * 128;

    int lr = tid >> 2;            // 0..63
    int lc = (tid & 3) * 4;       // 0,4,8,12
    const float* pA0 = &A[(size_t)(m0 + lr) * FEATD + lc];
    const float* pA1 = &A[(size_t)(m0 + 64 + lr) * FEATD + lc];
    const float* pB0 = &W[(size_t)(n0 + lr) * FEATD + lc];
    const float* pB1 = &W[(size_t)(n0 + 64 + lr) * FEATD + lc];

    u64 acc2[8][4];
#pragma unroll
    for (int i = 0; i < 8; i++)
#pragma unroll
        for (int jp = 0; jp < 4; jp++) acc2[i][jp] = 0ull;

    // prologue: load tile 0
    float4 pa0 = *(const float4*)pA0;
    float4 pa1 = *(const float4*)pA1;
    float4 pb0 = *(const float4*)pB0;
    float4 pb1 = *(const float4*)pB1;
    As[0][lc + 0][lr] = pa0.x; As[0][lc + 1][lr] = pa0.y;
    As[0][lc + 2][lr] = pa0.z; As[0][lc + 3][lr] = pa0.w;
    As[0][lc + 0][64 + lr] = pa1.x; As[0][lc + 1][64 + lr] = pa1.y;
    As[0][lc + 2][64 + lr] = pa1.z; As[0][lc + 3][64 + lr] = pa1.w;
    Bs[0][lc + 0][lr] = pb0.x; Bs[0][lc + 1][lr] = pb0.y;
    Bs[0][lc + 2][lr] = pb0.z; Bs[0][lc + 3][lr] = pb0.w;
    Bs[0][lc + 0][64 + lr] = pb1.x; Bs[0][lc + 1][64 + lr] = pb1.y;
    Bs[0][lc + 2][64 + lr] = pb1.z; Bs[0][lc + 3][64 + lr] = pb1.w;
    __syncthreads();

    int cur = 0;
    for (int k0 = 16; k0 <= FEATD; k0 += 16) {
        bool more = (k0 < FEATD);
        if (more) {
            pa0 = *(const float4*)(pA0 + k0);
            pa1 = *(const float4*)(pA1 + k0);
            pb0 = *(const float4*)(pB0 + k0);
            pb1 = *(const float4*)(pB1 + k0);
        }
#pragma unroll
        for (int kk = 0; kk < 16; kk++) {
            float af[8];
            *(float4*)&af[0] = *(const float4*)&As[cur][kk][ty * 4];
            *(float4*)&af[4] = *(const float4*)&As[cur][kk][64 + ty * 4];
            union { float4 v[2]; u64 p[4]; } B;
            B.v[0] = *(const float4*)&Bs[cur][kk][tx * 4];
            B.v[1] = *(const float4*)&Bs[cur][kk][64 + tx * 4];
            u64 ap[8];
#pragma unroll
            for (int i = 0; i < 8; i++) ap[i] = pack2(af[i], af[i]);
#pragma unroll
            for (int i = 0; i < 8; i++)
#pragma unroll
                for (int jp = 0; jp < 4; jp++)
                    fma2(acc2[i][jp], ap[i], B.p[jp]);
        }
        if (more) {
            int nxt = cur ^ 1;
            As[nxt][lc + 0][lr] = pa0.x; As[nxt][lc + 1][lr] = pa0.y;
            As[nxt][lc + 2][lr] = pa0.z; As[nxt][lc + 3][lr] = pa0.w;
            As[nxt][lc + 0][64 + lr] = pa1.x; As[nxt][lc + 1][64 + lr] = pa1.y;
            As[nxt][lc + 2][64 + lr] = pa1.z; As[nxt][lc + 3][64 + lr] = pa1.w;
            Bs[nxt][lc + 0][lr] = pb0.x; Bs[nxt][lc + 1][lr] = pb0.y;
            Bs[nxt][lc + 2][lr] = pb0.z; Bs[nxt][lc + 3][lr] = pb0.w;
            Bs[nxt][lc + 0][64 + lr] = pb1.x; Bs[nxt][lc + 1][64 + lr] = pb1.y;
            Bs[nxt][lc + 2][64 + lr] = pb1.z; Bs[nxt][lc + 3][64 + lr] = pb1.w;
        }
        __syncthreads();
        cur ^= 1;
    }

    // epilogue
#pragma unroll
    for (int i = 0; i < 8; i++) {
        int row = m0 + ((i < 4) ? (ty * 4 + i) : (64 + ty * 4 + (i - 4)));
#pragma unroll
        for (int jh = 0; jh < 2; jh++) {
            int col0 = n0 + jh * 64 + tx * 4;
            float2 e0 = unpack2(acc2[i][jh * 2 + 0]);
            float2 e1 = unpack2(acc2[i][jh * 2 + 1]);
            float v[4] = {e0.x, e0.y, e1.x, e1.y};
#pragma unroll
            for (int jj = 0; jj < 4; jj++) {
                int o = col0 + jj;
                if (bias) v[jj] += __ldg(&bias[o]);
                if (uadd) v[jj] += __ldg(&uadd[o]);
                v[jj] *= scale;
            }
            int gidx = col0 >> 6, d = col0 & 63;
            *(float4*)&outp[((size_t)gidx * rows + row) * DG + d] =
                make_float4(v[0], v[1], v[2], v[3]);
        }
    }
}

// =====================================================================
// Kernel 3: fused flash attention + epilogue, f32x2-packed.
// =====================================================================
#define STR 68
#define ATT_SMEM_BYTES (4 * 64 * STR * 4)

__global__ __launch_bounds__(256) void attn_kernel(
    float* __restrict__ out, const float* __restrict__ Wv_b)
{
    extern __shared__ float sm[];
    float* Qs = sm;
    float* Ks = sm + 64 * STR;
    float* Vs = sm + 2 * 64 * STR;
    float* Ps = sm + 3 * 64 * STR;

    int tid = threadIdx.x;
    int tx = tid & 15, ty = tid >> 4;
    int g  = blockIdx.y;
    int n0 = blockIdx.x * 64;

#pragma unroll
    for (int b = 0; b < 4; b++) {
        int fid = tid + b * 256;
        int r = fid >> 4, d4 = fid & 15;
        *(float4*)&Qs[r * STR + d4 * 4] =
            *(const float4*)&g_q[((size_t)g * NN + n0 + r) * DG + d4 * 4];
    }

    float m_run[4], l_run[4];
    u64 accv[4][2];
#pragma unroll
    for (int i = 0; i < 4; i++) {
        m_run[i] = -CUDART_INF_F;
        l_run[i] = 0.0f;
        accv[i][0] = 0ull; accv[i][1] = 0ull;
    }

    const float* lwbase = g_logw + (size_t)g * NN * MMM + (size_t)n0 * MMM;

    for (int m0 = 0; m0 < MMM; m0 += 64) {
        __syncthreads();
#pragma unroll
        for (int b = 0; b < 4; b++) {
            int fid = tid + b * 256;
            int r = fid >> 4, d4 = fid & 15;
            size_t src = ((size_t)g * MMM + m0 + r) * DG + d4 * 4;
            *(float4*)&Ks[r * STR + d4 * 4] = *(const float4*)&g_k[src];
            *(float4*)&Vs[r * STR + d4 * 4] = *(const float4*)&g_v[src];
        }
        __syncthreads();

        // ---- S = logw + Q K^T, packed over d ----
        u64 s2[4][4];
#pragma unroll
        for (int i = 0; i < 4; i++)
#pragma unroll
            for (int j = 0; j < 4; j++)
                s2[i][j] = pack2(lwbase[(size_t)(ty * 4 + i) * MMM + m0 + tx + 16 * j], 0.0f);
#pragma unroll
        for (int d4 = 0; d4 < 16; d4++) {
            F4u qf[4], kf[4];
#pragma unroll
            for (int i = 0; i < 4; i++) qf[i].v = *(float4*)&Qs[(ty * 4 + i) * STR + d4 * 4];
#pragma unroll
            for (int j = 0; j < 4; j++) kf[j].v = *(float4*)&Ks[(tx + 16 * j) * STR + d4 * 4];
#pragma unroll
            for (int i = 0; i < 4; i++)
#pragma unroll
                for (int j = 0; j < 4; j++) {
                    fma2(s2[i][j], qf[i].p[0], kf[j].p[0]);
                    fma2(s2[i][j], qf[i].p[1], kf[j].p[1]);
                }
        }
        float s[4][4];
#pragma unroll
        for (int i = 0; i < 4; i++)
#pragma unroll
            for (int j = 0; j < 4; j++) {
                float2 t = unpack2(s2[i][j]);
                s[i][j] = t.x + t.y;
            }

        // ---- online softmax (stats replicated across tx lanes) ----
#pragma unroll
        for (int i = 0; i < 4; i++) {
            float rm = fmaxf(fmaxf(s[i][0], s[i][1]), fmaxf(s[i][2], s[i][3]));
#pragma unroll
            for (int o = 1; o < 16; o <<= 1)
                rm = fmaxf(rm, __shfl_xor_sync(0xffffffffu, rm, o));
            float mnew  = fmaxf(m_run[i], rm);
            float alpha = __expf(m_run[i] - mnew);   // first iter: exp(-inf)=0
            m_run[i] = mnew;
            float rs = 0.0f;
#pragma unroll
            for (int j = 0; j < 4; j++) {
                s[i][j] = __expf(s[i][j] - mnew);
                rs += s[i][j];
            }
#pragma unroll
            for (int o = 1; o < 16; o <<= 1)
                rs += __shfl_xor_sync(0xffffffffu, rs, o);
            l_run[i] = l_run[i] * alpha + rs;
            u64 apk = pack2(alpha, alpha);
            mul2(accv[i][0], apk);
            mul2(accv[i][1], apk);
#pragma unroll
            for (int j = 0; j < 4; j++)
                Ps[(ty * 4 + i) * STR + tx + 16 * j] = s[i][j];
        }
        __syncthreads();

        // ---- acc += P @ V, packed over output dims ----
#pragma unroll 4
        for (int mm = 0; mm < 64; mm += 4) {
            F4u vf[4];
#pragma unroll
            for (int t = 0; t < 4; t++)
                vf[t].v = *(float4*)&Vs[(mm + t) * STR + tx * 4];
#pragma unroll
            for (int i = 0; i < 4; i++) {
                float4 pf4 = *(float4*)&Ps[(ty * 4 + i) * STR + mm];
                u64 p0 = pack2(pf4.x, pf4.x), p1 = pack2(pf4.y, pf4.y);
                u64 p2 = pack2(pf4.z, pf4.z), p3 = pack2(pf4.w, pf4.w);
                fma2(accv[i][0], p0, vf[0].p[0]); fma2(accv[i][1], p0, vf[0].p[1]);
                fma2(accv[i][0], p1, vf[1].p[0]); fma2(accv[i][1], p1, vf[1].p[1]);
                fma2(accv[i][0], p2, vf[2].p[0]); fma2(accv[i][1], p2, vf[2].p[1]);
                fma2(accv[i][0], p3, vf[3].p[0]); fma2(accv[i][1], p3, vf[3].p[1]);
            }
        }
    }

    // ---- epilogue: normalize + Wv_b ----
#pragma unroll
    for (int i = 0; i < 4; i++) {
        float inv = __frcp_rn(l_run[i]);
        int row = n0 + ty * 4 + i;
        int o0  = g * DG + tx * 4;
        float4 bv = *(const float4*)&Wv_b[o0];
        float2 a0 = unpack2(accv[i][0]);
        float2 a1 = unpack2(accv[i][1]);
        float4 r4 = make_float4(a0.x * inv + bv.x, a0.y * inv + bv.y,
                                a1.x * inv + bv.z, a1.y * inv + bv.w);
        *(float4*)&out[(size_t)row * FEATD + o0] = r4;
    }
}

// =====================================================================
extern "C" void kernel_launch(void* const* d_in, const int* in_sizes, int n_in,
                              void* d_out, int out_size) {
    const float* bbox     = (const float*)d_in[0];
    const float* ref_bbox = (const float*)d_in[1];
    const float* roi_feat = (const float*)d_in[2];
    const float* ref_feat = (const float*)d_in[3];
    const float* Wg_w     = (const float*)d_in[4];
    const float* Wg_b     = (const float*)d_in[5];
    const float* Wq_w     = (const float*)d_in[6];
    const float* Wq_b     = (const float*)d_in[7];
    const float* Wk_w     = (const float*)d_in[8];
    const float* Wk_b     = (const float*)d_in[9];
    const float* Wv_w     = (const float*)d_in[10];
    const float* Wv_b     = (const float*)d_in[11];
    const float* u        = (const float*)d_in[12];
    float* out = (float*)d_out;

    cudaFuncSetAttribute(attn_kernel,
                         cudaFuncAttributeMaxDynamicSharedMemorySize,
                         ATT_SMEM_BYTES);

    pos_kernel<<<(NN * MMM) / 256, 256>>>(bbox, ref_bbox, Wg_w, Wg_b);
    gemm3_kernel<<<dim3(MMM / 128, FEATD / 128, 3), 256>>>(
        roi_feat, ref_feat, Wq_w, Wq_b, u, Wk_w, Wk_b, Wv_w);
    attn_kernel<<<dim3(NN / 64, NG), 256, ATT_SMEM_BYTES>>>(out, Wv_b);
}

// round 6
// speedup vs baseline: 1.5198x; 1.0509x over previous
#include <cuda_runtime.h>
#include <math_constants.h>

#define NN   512
#define MMM  2048
#define FEATD 1024
#define NG   16
#define DG   64

typedef unsigned long long u64;

// ---------------- packed f32x2 helpers ----------------
__device__ __forceinline__ u64 pack2(float lo, float hi) {
    u64 r; asm("mov.b64 %0, {%1,%2};" : "=l"(r) : "f"(lo), "f"(hi)); return r;
}
__device__ __forceinline__ float2 unpack2(u64 a) {
    float2 v; asm("mov.b64 {%0,%1}, %2;" : "=f"(v.x), "=f"(v.y) : "l"(a)); return v;
}
__device__ __forceinline__ void fma2(u64 &d, u64 a, u64 b) {
    asm("fma.rn.f32x2 %0, %1, %2, %0;" : "+l"(d) : "l"(a), "l"(b));
}
__device__ __forceinline__ void mul2(u64 &d, u64 a) {
    asm("mul.rn.f32x2 %0, %0, %1;" : "+l"(d) : "l"(a));
}

union F4u { float4 v; u64 p[2]; };

// ---------------- device scratch (no allocations allowed) ----------------
__device__ float g_q[NG * NN * DG];
__device__ float g_k[NG * MMM * DG];
__device__ float g_v[NG * MMM * DG];
__device__ float g_logw[NG * NN * MMM];
// per-box trig tables: index (chan*8+f)*count + box, chan 0=w 1=h, .x=sin .y=cos
__device__ float2 g_trigN[16 * NN];
__device__ float2 g_trigM[16 * MMM];

__constant__ float c_sc[8] = {100.0f, 42.16965034f, 17.7827941f, 7.498942093f,
                              3.16227766f, 1.333521432f, 0.5623413252f, 0.2371373706f};

__device__ __forceinline__ void cw_sincos(float a, float &s, float &c) {
    float kq = rintf(a * 0.15915494309f);
    float r  = fmaf(kq, -6.2831855f, a);
    r        = fmaf(kq, 1.7484555e-7f, r);
    s = __sinf(r); c = __cosf(r);
}

// =====================================================================
// Kernel 0: per-box trig tables (one thread per box)
// =====================================================================
__global__ __launch_bounds__(256) void trig_kernel(
    const float* __restrict__ bbox, const float* __restrict__ ref_bbox)
{
    int i = blockIdx.x * 256 + threadIdx.x;   // 0 .. NN+MMM-1
    bool isN = (i < NN);
    int b = isN ? i : i - NN;
    if (!isN && b >= MMM) return;
    const float* src = isN ? bbox : ref_bbox;
    float2* dst = isN ? g_trigN : g_trigM;
    int cnt = isN ? NN : MMM;

    float x0 = src[4 * b + 0], y0 = src[4 * b + 1];
    float x1 = src[4 * b + 2], y1 = src[4 * b + 3];
    float lw = __logf(x1 - x0 + 1.0f);
    float lh = __logf(y1 - y0 + 1.0f);
#pragma unroll
    for (int chan = 0; chan < 2; chan++) {
        float v = chan ? lh : lw;
#pragma unroll
        for (int f = 0; f < 8; f++) {
            float s, c;
            cw_sincos(v * c_sc[f], s, c);
            dst[(chan * 8 + f) * cnt + b] = make_float2(s, c);
        }
    }
}

// =====================================================================
// Kernel 1: position embedding -> grouped 1x1 conv -> log prior
// n constant per block; dw/dh trig via angle-difference of tables
// =====================================================================
__global__ __launch_bounds__(256, 2) void pos_kernel(
    const float* __restrict__ bbox, const float* __restrict__ ref_bbox,
    const float* __restrict__ Wg_w, const float* __restrict__ Wg_b)
{
    __shared__ float sW[NG * 64];
    __shared__ float sB[NG];
    int tid = threadIdx.x;
    for (int i = tid; i < NG * 64; i += 256) sW[i] = Wg_w[i];
    if (tid < NG) sB[tid] = Wg_b[tid];
    __syncthreads();

    int n = blockIdx.x >> 3;                       // 8 blocks per n
    int m = ((blockIdx.x & 7) << 8) + tid;

    float x0 = bbox[4 * n + 0], y0 = bbox[4 * n + 1];
    float x1 = bbox[4 * n + 2], y1 = bbox[4 * n + 3];
    float w  = x1 - x0 + 1.0f, h = y1 - y0 + 1.0f;
    float cx = 0.5f * (x0 + x1), cy = 0.5f * (y0 + y1);
    float rw = __frcp_rn(w), rh = __frcp_rn(h);

    float a0 = ref_bbox[4 * m + 0], a1 = ref_bbox[4 * m + 1];
    float a2 = ref_bbox[4 * m + 2], a3 = ref_bbox[4 * m + 3];
    float cxr = 0.5f * (a0 + a2), cyr = 0.5f * (a1 + a3);

    float dx = __logf(fabsf((cx - cxr) * rw) + 1e-3f);
    float dy = __logf(fabsf((cy - cyr) * rh) + 1e-3f);

    u64 svp[16], cvp[16];

    // c=0 (dx), c=1 (dy): full per-thread trig
#pragma unroll
    for (int c = 0; c < 2; c++) {
        float p = c ? dy : dx;
#pragma unroll
        for (int fp = 0; fp < 4; fp++) {
            float s0, c0, s1, c1;
            cw_sincos(p * c_sc[2 * fp],     s0, c0);
            cw_sincos(p * c_sc[2 * fp + 1], s1, c1);
            svp[c * 4 + fp] = pack2(s0, s1);
            cvp[c * 4 + fp] = pack2(c0, c1);
        }
    }

    // c=2 (dw), c=3 (dh): sin(aN-aM) = sN*cM - cN*sM ; cos = cN*cM + sN*sM
#pragma unroll
    for (int chan = 0; chan < 2; chan++) {
        float sd[8], cd[8];
#pragma unroll
        for (int f = 0; f < 8; f++) {
            float2 tN = g_trigN[(chan * 8 + f) * NN + n];     // broadcast
            float2 tM = g_trigM[(chan * 8 + f) * MMM + m];    // coalesced
            sd[f] = tN.x * tM.y - tN.y * tM.x;
            cd[f] = fmaf(tN.y, tM.y, tN.x * tM.x);
        }
#pragma unroll
        for (int fp = 0; fp < 4; fp++) {
            svp[8 + chan * 4 + fp] = pack2(sd[2 * fp], sd[2 * fp + 1]);
            cvp[8 + chan * 4 + fp] = pack2(cd[2 * fp], cd[2 * fp + 1]);
        }
    }

    int base = n * MMM + m;
#pragma unroll
    for (int gi = 0; gi < NG; gi++) {
        u64 acc = pack2(sB[gi], 0.0f);
        const float* wg = &sW[gi * 64];
#pragma unroll
        for (int c = 0; c < 4; c++) {
            F4u wlo, whi, klo, khi;
            wlo.v = *(const float4*)&wg[c * 16 + 0];
            whi.v = *(const float4*)&wg[c * 16 + 4];
            klo.v = *(const float4*)&wg[c * 16 + 8];
            khi.v = *(const float4*)&wg[c * 16 + 12];
            fma2(acc, wlo.p[0], svp[c * 4 + 0]);
            fma2(acc, wlo.p[1], svp[c * 4 + 1]);
            fma2(acc, whi.p[0], svp[c * 4 + 2]);
            fma2(acc, whi.p[1], svp[c * 4 + 3]);
            fma2(acc, klo.p[0], cvp[c * 4 + 0]);
            fma2(acc, klo.p[1], cvp[c * 4 + 1]);
            fma2(acc, khi.p[0], cvp[c * 4 + 2]);
            fma2(acc, khi.p[1], cvp[c * 4 + 3]);
        }
        float2 t2 = unpack2(acc);
        float pf = fmaxf(t2.x + t2.y, 0.0f);
        g_logw[(size_t)gi * (NN * MMM) + base] = __logf(pf + 1e-6f);
    }
}

// =====================================================================
// Kernel 2: fused Q/K/V SGEMM, double-buffered, f32x2-packed
// =====================================================================
__global__ __launch_bounds__(256, 2) void gemm3_kernel(
    const float* __restrict__ roi, const float* __restrict__ ref,
    const float* __restrict__ Wq, const float* __restrict__ Wqb,
    const float* __restrict__ uvec,
    const float* __restrict__ Wk, const float* __restrict__ Wkb,
    const float* __restrict__ Wv)
{
    __shared__ float As[2][16][128];
    __shared__ float Bs[2][16][128];

    int which = blockIdx.z;
    const float *A, *W, *bias, *uadd;
    float scale; int rows; float* outp;
    if (which == 0) {
        if (blockIdx.x >= NN / 128) return;
        A = roi; W = Wq; bias = Wqb; uadd = uvec; scale = 0.125f; rows = NN;  outp = g_q;
    } else if (which == 1) {
        A = ref; W = Wk; bias = Wkb; uadd = nullptr; scale = 1.0f; rows = MMM; outp = g_k;
    } else {
        A = ref; W = Wv; bias = nullptr; uadd = nullptr; scale = 1.0f; rows = MMM; outp = g_v;
    }

    int tid = threadIdx.x;
    int tx = tid & 15, ty = tid >> 4;
    int m0 = blockIdx.x * 128;
    int n0 = blockIdx.y * 128;

    int lr = tid >> 2;
    int lc = (tid & 3) * 4;
    const float* pA0 = &A[(size_t)(m0 + lr) * FEATD + lc];
    const float* pA1 = &A[(size_t)(m0 + 64 + lr) * FEATD + lc];
    const float* pB0 = &W[(size_t)(n0 + lr) * FEATD + lc];
    const float* pB1 = &W[(size_t)(n0 + 64 + lr) * FEATD + lc];

    u64 acc2[8][4];
#pragma unroll
    for (int i = 0; i < 8; i++)
#pragma unroll
        for (int jp = 0; jp < 4; jp++) acc2[i][jp] = 0ull;

    float4 pa0 = *(const float4*)pA0;
    float4 pa1 = *(const float4*)pA1;
    float4 pb0 = *(const float4*)pB0;
    float4 pb1 = *(const float4*)pB1;
    As[0][lc + 0][lr] = pa0.x; As[0][lc + 1][lr] = pa0.y;
    As[0][lc + 2][lr] = pa0.z; As[0][lc + 3][lr] = pa0.w;
    As[0][lc + 0][64 + lr] = pa1.x; As[0][lc + 1][64 + lr] = pa1.y;
    As[0][lc + 2][64 + lr] = pa1.z; As[0][lc + 3][64 + lr] = pa1.w;
    Bs[0][lc + 0][lr] = pb0.x; Bs[0][lc + 1][lr] = pb0.y;
    Bs[0][lc + 2][lr] = pb0.z; Bs[0][lc + 3][lr] = pb0.w;
    Bs[0][lc + 0][64 + lr] = pb1.x; Bs[0][lc + 1][64 + lr] = pb1.y;
    Bs[0][lc + 2][64 + lr] = pb1.z; Bs[0][lc + 3][64 + lr] = pb1.w;
    __syncthreads();

    int cur = 0;
    for (int k0 = 16; k0 <= FEATD; k0 += 16) {
        bool more = (k0 < FEATD);
        if (more) {
            pa0 = *(const float4*)(pA0 + k0);
            pa1 = *(const float4*)(pA1 + k0);
            pb0 = *(const float4*)(pB0 + k0);
            pb1 = *(const float4*)(pB1 + k0);
        }
#pragma unroll
        for (int kk = 0; kk < 16; kk++) {
            float af[8];
            *(float4*)&af[0] = *(const float4*)&As[cur][kk][ty * 4];
            *(float4*)&af[4] = *(const float4*)&As[cur][kk][64 + ty * 4];
            union { float4 v[2]; u64 p[4]; } B;
            B.v[0] = *(const float4*)&Bs[cur][kk][tx * 4];
            B.v[1] = *(const float4*)&Bs[cur][kk][64 + tx * 4];
            u64 ap[8];
#pragma unroll
            for (int i = 0; i < 8; i++) ap[i] = pack2(af[i], af[i]);
#pragma unroll
            for (int i = 0; i < 8; i++)
#pragma unroll
                for (int jp = 0; jp < 4; jp++)
                    fma2(acc2[i][jp], ap[i], B.p[jp]);
        }
        if (more) {
            int nxt = cur ^ 1;
            As[nxt][lc + 0][lr] = pa0.x; As[nxt][lc + 1][lr] = pa0.y;
            As[nxt][lc + 2][lr] = pa0.z; As[nxt][lc + 3][lr] = pa0.w;
            As[nxt][lc + 0][64 + lr] = pa1.x; As[nxt][lc + 1][64 + lr] = pa1.y;
            As[nxt][lc + 2][64 + lr] = pa1.z; As[nxt][lc + 3][64 + lr] = pa1.w;
            Bs[nxt][lc + 0][lr] = pb0.x; Bs[nxt][lc + 1][lr] = pb0.y;
            Bs[nxt][lc + 2][lr] = pb0.z; Bs[nxt][lc + 3][lr] = pb0.w;
            Bs[nxt][lc + 0][64 + lr] = pb1.x; Bs[nxt][lc + 1][64 + lr] = pb1.y;
            Bs[nxt][lc + 2][64 + lr] = pb1.z; Bs[nxt][lc + 3][64 + lr] = pb1.w;
        }
        __syncthreads();
        cur ^= 1;
    }

#pragma unroll
    for (int i = 0; i < 8; i++) {
        int row = m0 + ((i < 4) ? (ty * 4 + i) : (64 + ty * 4 + (i - 4)));
#pragma unroll
        for (int jh = 0; jh < 2; jh++) {
            int col0 = n0 + jh * 64 + tx * 4;
            float2 e0 = unpack2(acc2[i][jh * 2 + 0]);
            float2 e1 = unpack2(acc2[i][jh * 2 + 1]);
            float v[4] = {e0.x, e0.y, e1.x, e1.y};
#pragma unroll
            for (int jj = 0; jj < 4; jj++) {
                int o = col0 + jj;
                if (bias) v[jj] += __ldg(&bias[o]);
                if (uadd) v[jj] += __ldg(&uadd[o]);
                v[jj] *= scale;
            }
            int gidx = col0 >> 6, d = col0 & 63;
            *(float4*)&outp[((size_t)gidx * rows + row) * DG + d] =
                make_float4(v[0], v[1], v[2], v[3]);
        }
    }
}

// =====================================================================
// Kernel 3: fused flash attention + epilogue, f32x2-packed
// =====================================================================
#define STR 68
#define ATT_SMEM_BYTES (4 * 64 * STR * 4)

__global__ __launch_bounds__(256) void attn_kernel(
    float* __restrict__ out, const float* __restrict__ Wv_b)
{
    extern __shared__ float sm[];
    float* Qs = sm;
    float* Ks = sm + 64 * STR;
    float* Vs = sm + 2 * 64 * STR;
    float* Ps = sm + 3 * 64 * STR;

    int tid = threadIdx.x;
    int tx = tid & 15, ty = tid >> 4;
    int g  = blockIdx.y;
    int n0 = blockIdx.x * 64;

#pragma unroll
    for (int b = 0; b < 4; b++) {
        int fid = tid + b * 256;
        int r = fid >> 4, d4 = fid & 15;
        *(float4*)&Qs[r * STR + d4 * 4] =
            *(const float4*)&g_q[((size_t)g * NN + n0 + r) * DG + d4 * 4];
    }

    float m_run[4], l_run[4];
    u64 accv[4][2];
#pragma unroll
    for (int i = 0; i < 4; i++) {
        m_run[i] = -CUDART_INF_F;
        l_run[i] = 0.0f;
        accv[i][0] = 0ull; accv[i][1] = 0ull;
    }

    const float* lwbase = g_logw + (size_t)g * NN * MMM + (size_t)n0 * MMM;

    for (int m0 = 0; m0 < MMM; m0 += 64) {
        __syncthreads();
#pragma unroll
        for (int b = 0; b < 4; b++) {
            int fid = tid + b * 256;
            int r = fid >> 4, d4 = fid & 15;
            size_t src = ((size_t)g * MMM + m0 + r) * DG + d4 * 4;
            *(float4*)&Ks[r * STR + d4 * 4] = *(const float4*)&g_k[src];
            *(float4*)&Vs[r * STR + d4 * 4] = *(const float4*)&g_v[src];
        }
        __syncthreads();

        u64 s2[4][4];
#pragma unroll
        for (int i = 0; i < 4; i++)
#pragma unroll
            for (int j = 0; j < 4; j++)
                s2[i][j] = pack2(lwbase[(size_t)(ty * 4 + i) * MMM + m0 + tx + 16 * j], 0.0f);
#pragma unroll
        for (int d4 = 0; d4 < 16; d4++) {
            F4u qf[4], kf[4];
#pragma unroll
            for (int i = 0; i < 4; i++) qf[i].v = *(float4*)&Qs[(ty * 4 + i) * STR + d4 * 4];
#pragma unroll
            for (int j = 0; j < 4; j++) kf[j].v = *(float4*)&Ks[(tx + 16 * j) * STR + d4 * 4];
#pragma unroll
            for (int i = 0; i < 4; i++)
#pragma unroll
                for (int j = 0; j < 4; j++) {
                    fma2(s2[i][j], qf[i].p[0], kf[j].p[0]);
                    fma2(s2[i][j], qf[i].p[1], kf[j].p[1]);
                }
        }
        float s[4][4];
#pragma unroll
        for (int i = 0; i < 4; i++)
#pragma unroll
            for (int j = 0; j < 4; j++) {
                float2 t = unpack2(s2[i][j]);
                s[i][j] = t.x + t.y;
            }

#pragma unroll
        for (int i = 0; i < 4; i++) {
            float rm = fmaxf(fmaxf(s[i][0], s[i][1]), fmaxf(s[i][2], s[i][3]));
#pragma unroll
            for (int o = 1; o < 16; o <<= 1)
                rm = fmaxf(rm, __shfl_xor_sync(0xffffffffu, rm, o));
            float mnew  = fmaxf(m_run[i], rm);
            float alpha = __expf(m_run[i] - mnew);
            m_run[i] = mnew;
            float rs = 0.0f;
#pragma unroll
            for (int j = 0; j < 4; j++) {
                s[i][j] = __expf(s[i][j] - mnew);
                rs += s[i][j];
            }
#pragma unroll
            for (int o = 1; o < 16; o <<= 1)
                rs += __shfl_xor_sync(0xffffffffu, rs, o);
            l_run[i] = l_run[i] * alpha + rs;
            u64 apk = pack2(alpha, alpha);
            mul2(accv[i][0], apk);
            mul2(accv[i][1], apk);
#pragma unroll
            for (int j = 0; j < 4; j++)
                Ps[(ty * 4 + i) * STR + tx + 16 * j] = s[i][j];
        }
        __syncthreads();

#pragma unroll 4
        for (int mm = 0; mm < 64; mm += 4) {
            F4u vf[4];
#pragma unroll
            for (int t = 0; t < 4; t++)
                vf[t].v = *(float4*)&Vs[(mm + t) * STR + tx * 4];
#pragma unroll
            for (int i = 0; i < 4; i++) {
                float4 pf4 = *(float4*)&Ps[(ty * 4 + i) * STR + mm];
                u64 p0 = pack2(pf4.x, pf4.x), p1 = pack2(pf4.y, pf4.y);
                u64 p2 = pack2(pf4.z, pf4.z), p3 = pack2(pf4.w, pf4.w);
                fma2(accv[i][0], p0, vf[0].p[0]); fma2(accv[i][1], p0, vf[0].p[1]);
                fma2(accv[i][0], p1, vf[1].p[0]); fma2(accv[i][1], p1, vf[1].p[1]);
                fma2(accv[i][0], p2, vf[2].p[0]); fma2(accv[i][1], p2, vf[2].p[1]);
                fma2(accv[i][0], p3, vf[3].p[0]); fma2(accv[i][1], p3, vf[3].p[1]);
            }
        }
    }

#pragma unroll
    for (int i = 0; i < 4; i++) {
        float inv = __frcp_rn(l_run[i]);
        int row = n0 + ty * 4 + i;
        int o0  = g * DG + tx * 4;
        float4 bv = *(const float4*)&Wv_b[o0];
        float2 a0 = unpack2(accv[i][0]);
        float2 a1 = unpack2(accv[i][1]);
        float4 r4 = make_float4(a0.x * inv + bv.x, a0.y * inv + bv.y,
                                a1.x * inv + bv.z, a1.y * inv + bv.w);
        *(float4*)&out[(size_t)row * FEATD + o0] = r4;
    }
}

// =====================================================================
extern "C" void kernel_launch(void* const* d_in, const int* in_sizes, int n_in,
                              void* d_out, int out_size) {
    const float* bbox     = (const float*)d_in[0];
    const float* ref_bbox = (const float*)d_in[1];
    const float* roi_feat = (const float*)d_in[2];
    const float* ref_feat = (const float*)d_in[3];
    const float* Wg_w     = (const float*)d_in[4];
    const float* Wg_b     = (const float*)d_in[5];
    const float* Wq_w     = (const float*)d_in[6];
    const float* Wq_b     = (const float*)d_in[7];
    const float* Wk_w     = (const float*)d_in[8];
    const float* Wk_b     = (const float*)d_in[9];
    const float* Wv_w     = (const float*)d_in[10];
    const float* Wv_b     = (const float*)d_in[11];
    const float* u        = (const float*)d_in[12];
    float* out = (float*)d_out;

    cudaFuncSetAttribute(attn_kernel,
                         cudaFuncAttributeMaxDynamicSharedMemorySize,
                         ATT_SMEM_BYTES);

    trig_kernel<<<(NN + MMM) / 256, 256>>>(bbox, ref_bbox);
    pos_kernel<<<(NN * MMM) / 256, 256>>>(bbox, ref_bbox, Wg_w, Wg_b);
    gemm3_kernel<<<dim3(MMM / 128, FEATD / 128, 3), 256>>>(
        roi_feat, ref_feat, Wq_w, Wq_b, u, Wk_w, Wk_b, Wv_w);
    attn_kernel<<<dim3(NN / 64, NG), 256, ATT_SMEM_BYTES>>>(out, Wv_b);
}